// round 1
// baseline (speedup 1.0000x reference)
#include <cuda_runtime.h>
#include <math.h>

#define NPOS 32768      // 32^3 fine positions
#define CIN 64
#define COFF 81         // 3 * 27 offset channels
#define COUT 32
#define CCHUNK 16

// Scratch (no allocs allowed -> __device__ globals)
__device__ float g_off[COFF * NPOS];            // offset conv output, [ch][pos]
__device__ float g_weff[8 * CIN * COFF * 8];    // parity-combined weights [par][c][o][j]
__device__ float g_scale[COUT];
__device__ float g_shift[COUT];

// ---------------------------------------------------------------------------
// K1: build parity-combined effective weights for the offset conv.
// A 3^3 conv on a 2x nearest-upsampled grid == per output parity an 8-tap
// conv on the coarse grid. For axis parity p and coarse-cell slot j in {0,1}:
//   p=0: j=0 -> taps {0},   j=1 -> taps {1,2}
//   p=1: j=0 -> taps {0,1}, j=1 -> taps {2}
// start = j*(1+p), count = (p!=j) ? 2 : 1.
// ---------------------------------------------------------------------------
__global__ void k_weff(const float* __restrict__ w_off) {
    int t = blockIdx.x * blockDim.x + threadIdx.x;
    if (t >= 8 * CIN * COFF * 8) return;
    int j  = t & 7;
    int o  = (t >> 3) % COFF;
    int c  = (t / (8 * COFF)) % CIN;
    int par = t / (8 * COFF * CIN);
    int pd = (par >> 2) & 1, ph = (par >> 1) & 1, pw = par & 1;
    int jd = (j >> 2) & 1,  jh = (j >> 1) & 1,  jw = j & 1;
    int sd = jd * (1 + pd), nd = (pd != jd) ? 2 : 1;
    int sh = jh * (1 + ph), nh = (ph != jh) ? 2 : 1;
    int sw = jw * (1 + pw), nw = (pw != jw) ? 2 : 1;
    const float* wb = w_off + (o * CIN + c) * 27;
    float s = 0.f;
    for (int a = 0; a < nd; a++)
        for (int bq = 0; bq < nh; bq++)
            for (int cc = 0; cc < nw; cc++)
                s += wb[(sd + a) * 9 + (sh + bq) * 3 + (sw + cc)];
    g_weff[t] = s;   // layout [par][c][o][j]
}

// ---------------------------------------------------------------------------
// K2: offset conv via the parity trick. Block = 128 coarse positions of one
// parity class. Each thread: acc[81] over 64 ch x 8 coarse cells.
// ---------------------------------------------------------------------------
__global__ void __launch_bounds__(128) k_offconv(const float* __restrict__ x,
                                                 const float* __restrict__ b_off) {
    __shared__ float sw[CCHUNK * COFF * 8];   // 41472 B
    int par  = blockIdx.x >> 5;
    int tile = blockIdx.x & 31;
    int q = tile * 128 + threadIdx.x;         // coarse linear index, 0..4095
    int qw = q & 15, qh = (q >> 4) & 15, qd = q >> 8;
    int pd = (par >> 2) & 1, ph = (par >> 1) & 1, pw = par & 1;

    int sp[8]; float msk[8];
    #pragma unroll
    for (int j = 0; j < 8; j++) {
        int cd = qd + pd - 1 + ((j >> 2) & 1);
        int ch = qh + ph - 1 + ((j >> 1) & 1);
        int cw = qw + pw - 1 + (j & 1);
        bool v = (unsigned)cd < 16u && (unsigned)ch < 16u && (unsigned)cw < 16u;
        sp[j]  = v ? ((cd * 16 + ch) * 16 + cw) : 0;
        msk[j] = v ? 1.f : 0.f;
    }

    float acc[COFF];
    #pragma unroll
    for (int o = 0; o < COFF; o++) acc[o] = 0.f;

    #pragma unroll 1
    for (int c0 = 0; c0 < CIN; c0 += CCHUNK) {
        __syncthreads();
        const float* gsrc = g_weff + ((size_t)(par * CIN + c0) * COFF) * 8;
        for (int i = threadIdx.x; i < CCHUNK * COFF * 8; i += 128)
            sw[i] = gsrc[i];
        __syncthreads();
        #pragma unroll 1
        for (int cc = 0; cc < CCHUNK; cc++) {
            const float* xb = x + (c0 + cc) * 4096;
            float xv[8];
            #pragma unroll
            for (int j = 0; j < 8; j++) xv[j] = msk[j] * __ldg(&xb[sp[j]]);
            const float4* wrow = (const float4*)(sw + cc * COFF * 8);
            #pragma unroll
            for (int o = 0; o < COFF; o++) {
                float4 wa = wrow[o * 2];
                float4 wb2 = wrow[o * 2 + 1];
                acc[o] += xv[0]*wa.x + xv[1]*wa.y + xv[2]*wa.z + xv[3]*wa.w
                        + xv[4]*wb2.x + xv[5]*wb2.y + xv[6]*wb2.z + xv[7]*wb2.w;
            }
        }
    }
    int df = 2*qd + pd, hf = 2*qh + ph, wf = 2*qw + pw;
    int p = (df * 32 + hf) * 32 + wf;
    #pragma unroll 1
    for (int o = 0; o < COFF; o++)
        g_off[o * NPOS + p] = acc[o] + b_off[o];
}

// ---------------------------------------------------------------------------
// K3: deformable sampling + 32x64 per-tap accumulation.
// Thread = one fine position; acc[32] in registers; per-tap weight slice
// staged in smem as [c][oc] so the oc-FMAs read broadcast float4s.
// Sampling reads x (coarse) directly: upsampled value at fine index f == x[f>>1].
// ---------------------------------------------------------------------------
__global__ void __launch_bounds__(128) k_deform(const float* __restrict__ x,
                                                const float* __restrict__ wmain,
                                                const float* __restrict__ bmain,
                                                float* __restrict__ out) {
    __shared__ float4 ws4[CIN * 8];   // [c][oc/4], 8 KB
    int p = blockIdx.x * 128 + threadIdx.x;
    int wf = p & 31, hf = (p >> 5) & 31, df = p >> 10;

    float acc[COUT];
    #pragma unroll
    for (int i = 0; i < COUT; i++) acc[i] = 0.f;

    #pragma unroll 1
    for (int tap = 0; tap < 27; tap++) {
        __syncthreads();
        for (int i = threadIdx.x; i < CIN * COUT; i += 128) {
            int c = i >> 5, oc = i & 31;
            ((float*)ws4)[c * 32 + oc] = wmain[(oc * CIN + c) * 27 + tap];
        }
        __syncthreads();

        int kd = tap / 9, kh = (tap / 3) % 3, kw = tap % 3;
        float pdc = (float)(df + kd - 1) + g_off[(tap * 3 + 0) * NPOS + p];
        float phc = (float)(hf + kh - 1) + g_off[(tap * 3 + 1) * NPOS + p];
        float pwc = (float)(wf + kw - 1) + g_off[(tap * 3 + 2) * NPOS + p];
        float fd0 = floorf(pdc), fh0 = floorf(phc), fw0 = floorf(pwc);
        int id0 = (int)fd0, ih0 = (int)fh0, iw0 = (int)fw0;
        float fd = pdc - fd0, fh = phc - fh0, fw = pwc - fw0;

        int addrs[8]; float wts[8];
        #pragma unroll
        for (int j = 0; j < 8; j++) {
            int fid = id0 + ((j >> 2) & 1);
            int fih = ih0 + ((j >> 1) & 1);
            int fiw = iw0 + (j & 1);
            bool v = (unsigned)fid < 32u && (unsigned)fih < 32u && (unsigned)fiw < 32u;
            int cd = fid >> 1, ch = fih >> 1, cw = fiw >> 1;
            addrs[j] = v ? ((cd * 16 + ch) * 16 + cw) : 0;
            float wd = ((j >> 2) & 1) ? fd : 1.f - fd;
            float wh = ((j >> 1) & 1) ? fh : 1.f - fh;
            float ww = (j & 1) ? fw : 1.f - fw;
            wts[j] = v ? wd * wh * ww : 0.f;
        }

        #pragma unroll 2
        for (int c = 0; c < CIN; c++) {
            const float* xb = x + c * 4096;
            float v = 0.f;
            #pragma unroll
            for (int j = 0; j < 8; j++) v += wts[j] * __ldg(&xb[addrs[j]]);
            #pragma unroll
            for (int k = 0; k < 8; k++) {
                float4 wv = ws4[c * 8 + k];
                acc[k*4+0] += v * wv.x;
                acc[k*4+1] += v * wv.y;
                acc[k*4+2] += v * wv.z;
                acc[k*4+3] += v * wv.w;
            }
        }
    }
    #pragma unroll
    for (int oc = 0; oc < COUT; oc++)
        out[oc * NPOS + p] = acc[oc] + bmain[oc];
}

// ---------------------------------------------------------------------------
// K4a: per-channel mean/var -> scale/shift.  K4b: normalize + ReLU in place.
// ---------------------------------------------------------------------------
__global__ void k_bnstat(const float* __restrict__ out,
                         const float* __restrict__ gamma,
                         const float* __restrict__ beta) {
    __shared__ float ssum[256], ssq[256];
    int ch = blockIdx.x;
    const float* base = out + ch * NPOS;
    float s = 0.f, sq = 0.f;
    for (int i = threadIdx.x; i < NPOS; i += 256) {
        float v = base[i];
        s += v; sq += v * v;
    }
    ssum[threadIdx.x] = s; ssq[threadIdx.x] = sq;
    __syncthreads();
    for (int st = 128; st > 0; st >>= 1) {
        if (threadIdx.x < st) {
            ssum[threadIdx.x] += ssum[threadIdx.x + st];
            ssq[threadIdx.x]  += ssq[threadIdx.x + st];
        }
        __syncthreads();
    }
    if (threadIdx.x == 0) {
        float mean = ssum[0] * (1.f / (float)NPOS);
        float var  = ssq[0] * (1.f / (float)NPOS) - mean * mean;
        float inv  = rsqrtf(var + 1e-5f);
        float a = gamma[ch] * inv;
        g_scale[ch] = a;
        g_shift[ch] = beta[ch] - mean * a;
    }
}

__global__ void k_bnapply(float* __restrict__ out) {
    int idx = blockIdx.x * 256 + threadIdx.x;
    int ch = idx >> 15;
    float v = out[idx] * g_scale[ch] + g_shift[ch];
    out[idx] = fmaxf(v, 0.f);
}

extern "C" void kernel_launch(void* const* d_in, const int* in_sizes, int n_in,
                              void* d_out, int out_size) {
    const float* x     = (const float*)d_in[0];   // (1,64,16,16,16)
    const float* w_off = (const float*)d_in[1];   // (81,64,3,3,3)
    const float* b_off = (const float*)d_in[2];   // (81,)
    const float* w     = (const float*)d_in[3];   // (32,64,3,3,3)
    const float* b     = (const float*)d_in[4];   // (32,)
    const float* gamma = (const float*)d_in[5];   // (32,)
    const float* beta  = (const float*)d_in[6];   // (32,)
    float* out = (float*)d_out;                   // (1,32,32,32,32)

    k_weff<<<(8 * CIN * COFF * 8) / 256, 256>>>(w_off);
    k_offconv<<<256, 128>>>(x, b_off);
    k_deform<<<256, 128>>>(x, w, b, out);
    k_bnstat<<<COUT, 256>>>(out, gamma, beta);
    k_bnapply<<<4096, 256>>>(out);
}

// round 2
// speedup vs baseline: 1.0369x; 1.0369x over previous
#include <cuda_runtime.h>
#include <math.h>

#define NPOS 32768      // 32^3 fine positions
#define CIN 64
#define COFF 81         // 3 * 27 offset channels
#define COUT 32
#define CCHUNK 16

// Scratch (no allocs allowed -> __device__ globals)
__device__ float g_off[COFF * NPOS];            // offset conv output, [ch][pos]
__device__ float g_weff[8 * CIN * COFF * 8];    // parity-combined weights [par][c][o][j]
__device__ float g_scale[COUT];
__device__ float g_shift[COUT];

// ---------------------------------------------------------------------------
// K1: parity-combined effective weights for the offset conv (2x nearest
// upsample + 3^3 conv == per-parity 8-tap conv on the coarse grid).
// ---------------------------------------------------------------------------
__global__ void k_weff(const float* __restrict__ w_off) {
    int t = blockIdx.x * blockDim.x + threadIdx.x;
    if (t >= 8 * CIN * COFF * 8) return;
    int j  = t & 7;
    int o  = (t >> 3) % COFF;
    int c  = (t / (8 * COFF)) % CIN;
    int par = t / (8 * COFF * CIN);
    int pd = (par >> 2) & 1, ph = (par >> 1) & 1, pw = par & 1;
    int jd = (j >> 2) & 1,  jh = (j >> 1) & 1,  jw = j & 1;
    int sd = jd * (1 + pd), nd = (pd != jd) ? 2 : 1;
    int sh = jh * (1 + ph), nh = (ph != jh) ? 2 : 1;
    int sw = jw * (1 + pw), nw = (pw != jw) ? 2 : 1;
    const float* wb = w_off + (o * CIN + c) * 27;
    float s = 0.f;
    for (int a = 0; a < nd; a++)
        for (int bq = 0; bq < nh; bq++)
            for (int cc = 0; cc < nw; cc++)
                s += wb[(sd + a) * 9 + (sh + bq) * 3 + (sw + cc)];
    g_weff[t] = s;   // layout [par][c][o][j]
}

// ---------------------------------------------------------------------------
// K2: offset conv via the parity trick. Block = 128 coarse positions of one
// parity class. Each thread: acc[81] over 64 ch x 8 coarse cells.
// ---------------------------------------------------------------------------
__global__ void __launch_bounds__(128) k_offconv(const float* __restrict__ x,
                                                 const float* __restrict__ b_off) {
    __shared__ float sw[CCHUNK * COFF * 8];   // 41472 B
    int par  = blockIdx.x >> 5;
    int tile = blockIdx.x & 31;
    int q = tile * 128 + threadIdx.x;         // coarse linear index, 0..4095
    int qw = q & 15, qh = (q >> 4) & 15, qd = q >> 8;
    int pd = (par >> 2) & 1, ph = (par >> 1) & 1, pw = par & 1;

    int sp[8]; float msk[8];
    #pragma unroll
    for (int j = 0; j < 8; j++) {
        int cd = qd + pd - 1 + ((j >> 2) & 1);
        int ch = qh + ph - 1 + ((j >> 1) & 1);
        int cw = qw + pw - 1 + (j & 1);
        bool v = (unsigned)cd < 16u && (unsigned)ch < 16u && (unsigned)cw < 16u;
        sp[j]  = v ? ((cd * 16 + ch) * 16 + cw) : 0;
        msk[j] = v ? 1.f : 0.f;
    }

    float acc[COFF];
    #pragma unroll
    for (int o = 0; o < COFF; o++) acc[o] = 0.f;

    #pragma unroll 1
    for (int c0 = 0; c0 < CIN; c0 += CCHUNK) {
        __syncthreads();
        const float* gsrc = g_weff + ((size_t)(par * CIN + c0) * COFF) * 8;
        for (int i = threadIdx.x; i < CCHUNK * COFF * 8; i += 128)
            sw[i] = gsrc[i];
        __syncthreads();
        #pragma unroll 1
        for (int cc = 0; cc < CCHUNK; cc++) {
            const float* xb = x + (c0 + cc) * 4096;
            float xv[8];
            #pragma unroll
            for (int j = 0; j < 8; j++) xv[j] = msk[j] * __ldg(&xb[sp[j]]);
            const float4* wrow = (const float4*)(sw + cc * COFF * 8);
            #pragma unroll
            for (int o = 0; o < COFF; o++) {
                float4 wa = wrow[o * 2];
                float4 wb2 = wrow[o * 2 + 1];
                acc[o] += xv[0]*wa.x + xv[1]*wa.y + xv[2]*wa.z + xv[3]*wa.w
                        + xv[4]*wb2.x + xv[5]*wb2.y + xv[6]*wb2.z + xv[7]*wb2.w;
            }
        }
    }
    int df = 2*qd + pd, hf = 2*qh + ph, wf = 2*qw + pw;
    int p = (df * 32 + hf) * 32 + wf;
    #pragma unroll 1
    for (int o = 0; o < COFF; o++)
        g_off[o * NPOS + p] = acc[o] + b_off[o];
}

// ---------------------------------------------------------------------------
// K3: deformable sampling + per-tap GEMM-let, 4-way channel split.
// Block = 64 positions x 4 channel-quarters (256 threads). Each thread
// accumulates acc[32] over its 16 channels; tree-reduce in smem at the end.
// ---------------------------------------------------------------------------
__global__ void __launch_bounds__(256, 2) k_deform(const float* __restrict__ x,
                                                   const float* __restrict__ wmain,
                                                   const float* __restrict__ bmain,
                                                   float* __restrict__ out) {
    __shared__ float ws[CIN * COUT];          // per-tap weights [c][oc], 8 KB
    __shared__ float red[2 * 64 * 33];        // reduction, padded vs bank conflicts
    int tid  = threadIdx.x;
    int posi = tid & 63;
    int cs   = tid >> 6;                      // channel quarter 0..3
    int p = blockIdx.x * 64 + posi;
    int wf = p & 31, hf = (p >> 5) & 31, df = p >> 10;

    float acc[COUT];
    #pragma unroll
    for (int i = 0; i < COUT; i++) acc[i] = 0.f;

    #pragma unroll 1
    for (int tap = 0; tap < 27; tap++) {
        __syncthreads();
        for (int i = tid; i < CIN * COUT; i += 256) {
            int c = i >> 5, oc = i & 31;
            ws[c * 32 + oc] = wmain[(oc * CIN + c) * 27 + tap];
        }
        __syncthreads();

        int kd = tap / 9, kh = (tap / 3) % 3, kw = tap % 3;
        float pdc = (float)(df + kd - 1) + g_off[(tap * 3 + 0) * NPOS + p];
        float phc = (float)(hf + kh - 1) + g_off[(tap * 3 + 1) * NPOS + p];
        float pwc = (float)(wf + kw - 1) + g_off[(tap * 3 + 2) * NPOS + p];
        float fd0 = floorf(pdc), fh0 = floorf(phc), fw0 = floorf(pwc);
        int id0 = (int)fd0, ih0 = (int)fh0, iw0 = (int)fw0;
        float fd = pdc - fd0, fh = phc - fh0, fw = pwc - fw0;

        int addrs[8]; float wts[8];
        #pragma unroll
        for (int j = 0; j < 8; j++) {
            int fid = id0 + ((j >> 2) & 1);
            int fih = ih0 + ((j >> 1) & 1);
            int fiw = iw0 + (j & 1);
            bool v = (unsigned)fid < 32u && (unsigned)fih < 32u && (unsigned)fiw < 32u;
            int cd = fid >> 1, ch = fih >> 1, cw = fiw >> 1;
            addrs[j] = v ? ((cd * 16 + ch) * 16 + cw) : 0;
            float wd = ((j >> 2) & 1) ? fd : 1.f - fd;
            float wh = ((j >> 1) & 1) ? fh : 1.f - fh;
            float ww = (j & 1) ? fw : 1.f - fw;
            wts[j] = v ? wd * wh * ww : 0.f;
        }

        const float* xbase = x + cs * 16 * 4096;
        #pragma unroll 2
        for (int cc = 0; cc < 16; cc++) {
            const float* xb = xbase + cc * 4096;
            float v = 0.f;
            #pragma unroll
            for (int j = 0; j < 8; j++) v += wts[j] * __ldg(&xb[addrs[j]]);
            const float4* wrow = (const float4*)(ws + (cs * 16 + cc) * 32);
            #pragma unroll
            for (int k = 0; k < 8; k++) {
                float4 wv = wrow[k];
                acc[k*4+0] += v * wv.x;
                acc[k*4+1] += v * wv.y;
                acc[k*4+2] += v * wv.z;
                acc[k*4+3] += v * wv.w;
            }
        }
    }

    // tree-reduce across the 4 channel quarters
    __syncthreads();
    if (cs >= 2) {
        float* dst = red + ((cs - 2) * 64 + posi) * 33;
        #pragma unroll
        for (int oc = 0; oc < COUT; oc++) dst[oc] = acc[oc];
    }
    __syncthreads();
    if (cs < 2) {
        const float* src = red + (cs * 64 + posi) * 33;
        #pragma unroll
        for (int oc = 0; oc < COUT; oc++) acc[oc] += src[oc];
    }
    __syncthreads();
    if (cs == 1) {
        float* dst = red + posi * 33;
        #pragma unroll
        for (int oc = 0; oc < COUT; oc++) dst[oc] = acc[oc];
    }
    __syncthreads();
    if (cs == 0) {
        const float* src = red + posi * 33;
        #pragma unroll
        for (int oc = 0; oc < COUT; oc++)
            out[oc * NPOS + p] = acc[oc] + src[oc] + bmain[oc];
    }
}

// ---------------------------------------------------------------------------
// K4a: per-channel mean/var -> scale/shift (1024-thread blocks).
// K4b: normalize + ReLU in place.
// ---------------------------------------------------------------------------
__global__ void __launch_bounds__(1024) k_bnstat(const float* __restrict__ out,
                                                 const float* __restrict__ gamma,
                                                 const float* __restrict__ beta) {
    __shared__ float ssum[1024], ssq[1024];
    int ch = blockIdx.x;
    const float* base = out + ch * NPOS;
    float s = 0.f, sq = 0.f;
    for (int i = threadIdx.x; i < NPOS; i += 1024) {
        float v = base[i];
        s += v; sq += v * v;
    }
    ssum[threadIdx.x] = s; ssq[threadIdx.x] = sq;
    __syncthreads();
    for (int st = 512; st > 0; st >>= 1) {
        if (threadIdx.x < st) {
            ssum[threadIdx.x] += ssum[threadIdx.x + st];
            ssq[threadIdx.x]  += ssq[threadIdx.x + st];
        }
        __syncthreads();
    }
    if (threadIdx.x == 0) {
        float mean = ssum[0] * (1.f / (float)NPOS);
        float var  = ssq[0] * (1.f / (float)NPOS) - mean * mean;
        float inv  = rsqrtf(var + 1e-5f);
        float a = gamma[ch] * inv;
        g_scale[ch] = a;
        g_shift[ch] = beta[ch] - mean * a;
    }
}

__global__ void k_bnapply(float* __restrict__ out) {
    int idx = blockIdx.x * 256 + threadIdx.x;
    int ch = idx >> 15;
    float v = out[idx] * g_scale[ch] + g_shift[ch];
    out[idx] = fmaxf(v, 0.f);
}

extern "C" void kernel_launch(void* const* d_in, const int* in_sizes, int n_in,
                              void* d_out, int out_size) {
    const float* x     = (const float*)d_in[0];   // (1,64,16,16,16)
    const float* w_off = (const float*)d_in[1];   // (81,64,3,3,3)
    const float* b_off = (const float*)d_in[2];   // (81,)
    const float* w     = (const float*)d_in[3];   // (32,64,3,3,3)
    const float* b     = (const float*)d_in[4];   // (32,)
    const float* gamma = (const float*)d_in[5];   // (32,)
    const float* beta  = (const float*)d_in[6];   // (32,)
    float* out = (float*)d_out;                   // (1,32,32,32,32)

    k_weff<<<(8 * CIN * COFF * 8) / 256, 256>>>(w_off);
    k_offconv<<<256, 128>>>(x, b_off);
    k_deform<<<512, 256>>>(x, w, b, out);
    k_bnstat<<<COUT, 1024>>>(out, gamma, beta);
    k_bnapply<<<4096, 256>>>(out);
}

// round 3
// speedup vs baseline: 1.3080x; 1.2615x over previous
#include <cuda_runtime.h>
#include <math.h>

#define NPOS 32768      // 32^3 fine positions
#define CIN 64
#define COFF 81         // 3 * 27 offset channels
#define COUT 32
#define CCHUNK 16

// Scratch (no allocs allowed -> __device__ globals)
__device__ float g_off[COFF * NPOS];            // offset conv output, [ch][pos]
__device__ float g_weff[8 * CIN * COFF * 8];    // parity-combined weights [par][c][o][j]
__device__ float g_wT[27 * CIN * COUT];         // main weights transposed [tap][c][oc]
__device__ float g_scale[COUT];
__device__ float g_shift[COUT];

// ---------------------------------------------------------------------------
// K0: transpose main conv weights to [tap][c][oc] (one-time, tiny).
// ---------------------------------------------------------------------------
__global__ void k_wT(const float* __restrict__ wmain) {
    int t = blockIdx.x * blockDim.x + threadIdx.x;
    if (t >= 27 * CIN * COUT) return;
    int oc  = t & 31;
    int c   = (t >> 5) & 63;
    int tap = t >> 11;
    g_wT[t] = wmain[(oc * CIN + c) * 27 + tap];
}

// ---------------------------------------------------------------------------
// K1: parity-combined effective weights for the offset conv (2x nearest
// upsample + 3^3 conv == per-parity 8-tap conv on the coarse grid).
// ---------------------------------------------------------------------------
__global__ void k_weff(const float* __restrict__ w_off) {
    int t = blockIdx.x * blockDim.x + threadIdx.x;
    if (t >= 8 * CIN * COFF * 8) return;
    int j  = t & 7;
    int o  = (t >> 3) % COFF;
    int c  = (t / (8 * COFF)) % CIN;
    int par = t / (8 * COFF * CIN);
    int pd = (par >> 2) & 1, ph = (par >> 1) & 1, pw = par & 1;
    int jd = (j >> 2) & 1,  jh = (j >> 1) & 1,  jw = j & 1;
    int sd = jd * (1 + pd), nd = (pd != jd) ? 2 : 1;
    int sh = jh * (1 + ph), nh = (ph != jh) ? 2 : 1;
    int sw = jw * (1 + pw), nw = (pw != jw) ? 2 : 1;
    const float* wb = w_off + (o * CIN + c) * 27;
    float s = 0.f;
    for (int a = 0; a < nd; a++)
        for (int bq = 0; bq < nh; bq++)
            for (int cc = 0; cc < nw; cc++)
                s += wb[(sd + a) * 9 + (sh + bq) * 3 + (sw + cc)];
    g_weff[t] = s;   // layout [par][c][o][j]
}

// ---------------------------------------------------------------------------
// K2: offset conv via the parity trick. Block = 128 coarse positions of one
// parity class. Each thread: acc[81] over 64 ch x 8 coarse cells.
// ---------------------------------------------------------------------------
__global__ void __launch_bounds__(128) k_offconv(const float* __restrict__ x,
                                                 const float* __restrict__ b_off) {
    __shared__ float sw[CCHUNK * COFF * 8];   // 41472 B
    int par  = blockIdx.x >> 5;
    int tile = blockIdx.x & 31;
    int q = tile * 128 + threadIdx.x;         // coarse linear index, 0..4095
    int qw = q & 15, qh = (q >> 4) & 15, qd = q >> 8;
    int pd = (par >> 2) & 1, ph = (par >> 1) & 1, pw = par & 1;

    int sp[8]; float msk[8];
    #pragma unroll
    for (int j = 0; j < 8; j++) {
        int cd = qd + pd - 1 + ((j >> 2) & 1);
        int ch = qh + ph - 1 + ((j >> 1) & 1);
        int cw = qw + pw - 1 + (j & 1);
        bool v = (unsigned)cd < 16u && (unsigned)ch < 16u && (unsigned)cw < 16u;
        sp[j]  = v ? ((cd * 16 + ch) * 16 + cw) : 0;
        msk[j] = v ? 1.f : 0.f;
    }

    float acc[COFF];
    #pragma unroll
    for (int o = 0; o < COFF; o++) acc[o] = 0.f;

    #pragma unroll 1
    for (int c0 = 0; c0 < CIN; c0 += CCHUNK) {
        __syncthreads();
        const float* gsrc = g_weff + ((size_t)(par * CIN + c0) * COFF) * 8;
        for (int i = threadIdx.x; i < CCHUNK * COFF * 8; i += 128)
            sw[i] = gsrc[i];
        __syncthreads();
        #pragma unroll 1
        for (int cc = 0; cc < CCHUNK; cc++) {
            const float* xb = x + (c0 + cc) * 4096;
            float xv[8];
            #pragma unroll
            for (int j = 0; j < 8; j++) xv[j] = msk[j] * __ldg(&xb[sp[j]]);
            const float4* wrow = (const float4*)(sw + cc * COFF * 8);
            #pragma unroll
            for (int o = 0; o < COFF; o++) {
                float4 wa = wrow[o * 2];
                float4 wb2 = wrow[o * 2 + 1];
                acc[o] += xv[0]*wa.x + xv[1]*wa.y + xv[2]*wa.z + xv[3]*wa.w
                        + xv[4]*wb2.x + xv[5]*wb2.y + xv[6]*wb2.z + xv[7]*wb2.w;
            }
        }
    }
    int df = 2*qd + pd, hf = 2*qh + ph, wf = 2*qw + pw;
    int p = (df * 32 + hf) * 32 + wf;
    #pragma unroll 1
    for (int o = 0; o < COFF; o++)
        g_off[o * NPOS + p] = acc[o] + b_off[o];
}

// ---------------------------------------------------------------------------
// K3: deformable sampling + per-tap GEMM-let, 4-way channel split.
// Block = 64 positions x 4 channel-quarters (256 threads). Per-tap weights
// now come from the pre-transposed g_wT -> fully coalesced smem staging.
// ---------------------------------------------------------------------------
__global__ void __launch_bounds__(256, 2) k_deform(const float* __restrict__ x,
                                                   const float* __restrict__ bmain,
                                                   float* __restrict__ out) {
    __shared__ float ws[CIN * COUT];          // per-tap weights [c][oc], 8 KB
    __shared__ float red[2 * 64 * 33];        // reduction, padded vs bank conflicts
    int tid  = threadIdx.x;
    int posi = tid & 63;
    int cs   = tid >> 6;                      // channel quarter 0..3
    int p = blockIdx.x * 64 + posi;
    int wf = p & 31, hf = (p >> 5) & 31, df = p >> 10;

    float acc[COUT];
    #pragma unroll
    for (int i = 0; i < COUT; i++) acc[i] = 0.f;

    #pragma unroll 1
    for (int tap = 0; tap < 27; tap++) {
        __syncthreads();
        {   // coalesced 8KB copy: g_wT[tap] is contiguous [c][oc]
            const float4* src = (const float4*)(g_wT + tap * CIN * COUT);
            float4* dst = (float4*)ws;
            for (int i = tid; i < CIN * COUT / 4; i += 256) dst[i] = src[i];
        }
        __syncthreads();

        int kd = tap / 9, kh = (tap / 3) % 3, kw = tap % 3;
        float pdc = (float)(df + kd - 1) + g_off[(tap * 3 + 0) * NPOS + p];
        float phc = (float)(hf + kh - 1) + g_off[(tap * 3 + 1) * NPOS + p];
        float pwc = (float)(wf + kw - 1) + g_off[(tap * 3 + 2) * NPOS + p];
        float fd0 = floorf(pdc), fh0 = floorf(phc), fw0 = floorf(pwc);
        int id0 = (int)fd0, ih0 = (int)fh0, iw0 = (int)fw0;
        float fd = pdc - fd0, fh = phc - fh0, fw = pwc - fw0;

        int addrs[8]; float wts[8];
        #pragma unroll
        for (int j = 0; j < 8; j++) {
            int fid = id0 + ((j >> 2) & 1);
            int fih = ih0 + ((j >> 1) & 1);
            int fiw = iw0 + (j & 1);
            bool v = (unsigned)fid < 32u && (unsigned)fih < 32u && (unsigned)fiw < 32u;
            int cd = fid >> 1, ch = fih >> 1, cw = fiw >> 1;
            addrs[j] = v ? ((cd * 16 + ch) * 16 + cw) : 0;
            float wd = ((j >> 2) & 1) ? fd : 1.f - fd;
            float wh = ((j >> 1) & 1) ? fh : 1.f - fh;
            float ww = (j & 1) ? fw : 1.f - fw;
            wts[j] = v ? wd * wh * ww : 0.f;
        }

        const float* xbase = x + cs * 16 * 4096;
        #pragma unroll 2
        for (int cc = 0; cc < 16; cc++) {
            const float* xb = xbase + cc * 4096;
            float v = 0.f;
            #pragma unroll
            for (int j = 0; j < 8; j++) v += wts[j] * __ldg(&xb[addrs[j]]);
            const float4* wrow = (const float4*)(ws + (cs * 16 + cc) * 32);
            #pragma unroll
            for (int k = 0; k < 8; k++) {
                float4 wv = wrow[k];
                acc[k*4+0] += v * wv.x;
                acc[k*4+1] += v * wv.y;
                acc[k*4+2] += v * wv.z;
                acc[k*4+3] += v * wv.w;
            }
        }
    }

    // tree-reduce across the 4 channel quarters
    __syncthreads();
    if (cs >= 2) {
        float* dst = red + ((cs - 2) * 64 + posi) * 33;
        #pragma unroll
        for (int oc = 0; oc < COUT; oc++) dst[oc] = acc[oc];
    }
    __syncthreads();
    if (cs < 2) {
        const float* src = red + (cs * 64 + posi) * 33;
        #pragma unroll
        for (int oc = 0; oc < COUT; oc++) acc[oc] += src[oc];
    }
    __syncthreads();
    if (cs == 1) {
        float* dst = red + posi * 33;
        #pragma unroll
        for (int oc = 0; oc < COUT; oc++) dst[oc] = acc[oc];
    }
    __syncthreads();
    if (cs == 0) {
        const float* src = red + posi * 33;
        #pragma unroll
        for (int oc = 0; oc < COUT; oc++)
            out[oc * NPOS + p] = acc[oc] + src[oc] + bmain[oc];
    }
}

// ---------------------------------------------------------------------------
// K4a: per-channel mean/var -> scale/shift (1024-thread blocks).
// K4b: normalize + ReLU in place.
// ---------------------------------------------------------------------------
__global__ void __launch_bounds__(1024) k_bnstat(const float* __restrict__ out,
                                                 const float* __restrict__ gamma,
                                                 const float* __restrict__ beta) {
    __shared__ float ssum[1024], ssq[1024];
    int ch = blockIdx.x;
    const float* base = out + ch * NPOS;
    float s = 0.f, sq = 0.f;
    for (int i = threadIdx.x; i < NPOS; i += 1024) {
        float v = base[i];
        s += v; sq += v * v;
    }
    ssum[threadIdx.x] = s; ssq[threadIdx.x] = sq;
    __syncthreads();
    for (int st = 512; st > 0; st >>= 1) {
        if (threadIdx.x < st) {
            ssum[threadIdx.x] += ssum[threadIdx.x + st];
            ssq[threadIdx.x]  += ssq[threadIdx.x + st];
        }
        __syncthreads();
    }
    if (threadIdx.x == 0) {
        float mean = ssum[0] * (1.f / (float)NPOS);
        float var  = ssq[0] * (1.f / (float)NPOS) - mean * mean;
        float inv  = rsqrtf(var + 1e-5f);
        float a = gamma[ch] * inv;
        g_scale[ch] = a;
        g_shift[ch] = beta[ch] - mean * a;
    }
}

__global__ void k_bnapply(float* __restrict__ out) {
    int idx = blockIdx.x * 256 + threadIdx.x;
    int ch = idx >> 15;
    float v = out[idx] * g_scale[ch] + g_shift[ch];
    out[idx] = fmaxf(v, 0.f);
}

extern "C" void kernel_launch(void* const* d_in, const int* in_sizes, int n_in,
                              void* d_out, int out_size) {
    const float* x     = (const float*)d_in[0];   // (1,64,16,16,16)
    const float* w_off = (const float*)d_in[1];   // (81,64,3,3,3)
    const float* b_off = (const float*)d_in[2];   // (81,)
    const float* w     = (const float*)d_in[3];   // (32,64,3,3,3)
    const float* b     = (const float*)d_in[4];   // (32,)
    const float* gamma = (const float*)d_in[5];   // (32,)
    const float* beta  = (const float*)d_in[6];   // (32,)
    float* out = (float*)d_out;                   // (1,32,32,32,32)

    k_wT<<<(27 * CIN * COUT + 255) / 256, 256>>>(w);
    k_weff<<<(8 * CIN * COFF * 8) / 256, 256>>>(w_off);
    k_offconv<<<256, 128>>>(x, b_off);
    k_deform<<<512, 256>>>(x, b, out);
    k_bnstat<<<COUT, 1024>>>(out, gamma, beta);
    k_bnapply<<<4096, 256>>>(out);
}